// round 1
// baseline (speedup 1.0000x reference)
#include <cuda_runtime.h>

// LTC scan, fused persistent SIMT kernel.
// B=512 batch rows are independent chains -> 128 CTAs x 4 rows, h in registers,
// W_r / W_in resident in shared memory (padded stride to avoid bank conflicts).
// Each thread owns one output index j for a PAIR of rows, so every W element
// loaded from shared feeds 2 FMAs (halves crossbar pressure vs naive).

#define Bsz 512
#define Ssz 512
#define Dsz 128
#define Hsz 128
#define PAD 132          // row stride in shared: 132*4B = 528B, 16B-aligned, conflict-free for lane-consecutive row reads
#define THREADS 256
#define ROWS 4           // batch rows per CTA
#define UNFOLDS 6

__device__ __forceinline__ float ftanh(float s) {
    // tanh(x) = 1 - 2/(exp(2x)+1); __expf -> MUFU.EX2, __fdividef -> MUFU.RCP
    float e = __expf(2.0f * s);
    return 1.0f - __fdividef(2.0f, e + 1.0f);
}

__global__ void __launch_bounds__(THREADS, 1)
ltc_kernel(const float* __restrict__ x,
           const float* __restrict__ W_in,
           const float* __restrict__ b_in,
           const float* __restrict__ W_r,
           const float* __restrict__ b_r,
           const float* __restrict__ W_fc,
           const float* __restrict__ b_fc,
           float* __restrict__ out)
{
    extern __shared__ float sm[];
    float* Wr_s  = sm;                     // [Hsz][PAD]
    float* Win_s = Wr_s + Hsz * PAD;       // [Hsz][PAD]
    float* h_s   = Win_s + Hsz * PAD;      // [2][ROWS][Hsz] double-buffered hidden state
    float* x_s   = h_s + 2 * ROWS * Hsz;   // [ROWS][Dsz]  (also reused as final reduce scratch)

    const int tid = threadIdx.x;

    // Stage weights into shared. Global reads and shared writes both coalesced
    // (no transpose: thread j iterates its own W row, padding fixes banks).
    for (int i = tid; i < Hsz * Dsz; i += THREADS) {
        int j = i >> 7, k = i & 127;
        Wr_s[j * PAD + k]  = W_r[i];
        Win_s[j * PAD + k] = W_in[i];
    }

    const int p  = tid >> 7;        // row-pair index 0/1
    const int j  = tid & 127;       // output index owned by this thread
    const int r0 = 2 * p, r1 = 2 * p + 1;
    const int base = blockIdx.x * ROWS;

    const float* xg0 = x + (size_t)(base + r0) * Ssz * Dsz;
    const float* xg1 = x + (size_t)(base + r1) * Ssz * Dsz;

    const float bi  = b_in[j];
    const float bb  = b_r[j];
    const float wfc = W_fc[j];

    const float* wir = &Win_s[j * PAD];
    const float* wrr = &Wr_s[j * PAD];

    float h0 = 0.0f, h1 = 0.0f;

    // Prefetch x for t=0
    float xa = xg0[j];
    float xb = xg1[j];

    for (int t = 0; t < Ssz; ++t) {
        x_s[r0 * Dsz + j] = xa;
        x_s[r1 * Dsz + j] = xb;
        __syncthreads();   // also orders the one-time weight fill before first use

        // Prefetch next timestep's x while we compute (hidden behind ~7 matvecs)
        if (t + 1 < Ssz) {
            xa = xg0[(size_t)(t + 1) * Dsz + j];
            xb = xg1[(size_t)(t + 1) * Dsz + j];
        }

        // xin = W_in @ x + b_in   (one matvec per row, W reused across the pair)
        float a00 = 0.f, a01 = 0.f, a02 = 0.f, a03 = 0.f;
        float a10 = 0.f, a11 = 0.f, a12 = 0.f, a13 = 0.f;
        #pragma unroll
        for (int k = 0; k < Dsz; k += 4) {
            float4 w  = *(const float4*)(wir + k);
            float4 va = *(const float4*)(x_s + r0 * Dsz + k);
            float4 vb = *(const float4*)(x_s + r1 * Dsz + k);
            a00 = fmaf(w.x, va.x, a00); a01 = fmaf(w.y, va.y, a01);
            a02 = fmaf(w.z, va.z, a02); a03 = fmaf(w.w, va.w, a03);
            a10 = fmaf(w.x, vb.x, a10); a11 = fmaf(w.y, vb.y, a11);
            a12 = fmaf(w.z, vb.z, a12); a13 = fmaf(w.w, vb.w, a13);
        }
        const float xin0 = bi + ((a00 + a01) + (a02 + a03));
        const float xin1 = bi + ((a10 + a11) + (a12 + a13));

        // 6 ODE unfolds: h = 0.9h + 0.1*tanh(xin + h@W_r^T + b_r)
        #pragma unroll 1
        for (int u = 0; u < UNFOLDS; ++u) {
            float* hb = h_s + (u & 1) * (ROWS * Hsz);   // alternate buffers -> one barrier/unfold
            hb[r0 * Hsz + j] = h0;
            hb[r1 * Hsz + j] = h1;
            __syncthreads();

            float c00 = 0.f, c01 = 0.f, c02 = 0.f, c03 = 0.f;
            float c10 = 0.f, c11 = 0.f, c12 = 0.f, c13 = 0.f;
            const float* hp0 = hb + r0 * Hsz;
            const float* hp1 = hb + r1 * Hsz;
            #pragma unroll
            for (int k = 0; k < Hsz; k += 4) {
                float4 w  = *(const float4*)(wrr + k);   // unique per thread
                float4 va = *(const float4*)(hp0 + k);   // warp broadcast
                float4 vb = *(const float4*)(hp1 + k);   // warp broadcast
                c00 = fmaf(w.x, va.x, c00); c01 = fmaf(w.y, va.y, c01);
                c02 = fmaf(w.z, va.z, c02); c03 = fmaf(w.w, va.w, c03);
                c10 = fmaf(w.x, vb.x, c10); c11 = fmaf(w.y, vb.y, c11);
                c12 = fmaf(w.z, vb.z, c12); c13 = fmaf(w.w, vb.w, c13);
            }
            const float s0 = xin0 + bb + ((c00 + c01) + (c02 + c03));
            const float s1 = xin1 + bb + ((c10 + c11) + (c12 + c13));
            h0 = 0.9f * h0 + 0.1f * ftanh(s0);
            h1 = 0.9f * h1 + 0.1f * ftanh(s1);
        }
    }

    // Final projection: out[b] = b_fc + sum_j h[b][j] * W_fc[j]
    __syncthreads();
    float* red = x_s;                 // reuse as [ROWS][Hsz] scratch
    red[r0 * Hsz + j] = h0 * wfc;
    red[r1 * Hsz + j] = h1 * wfc;
    __syncthreads();
    if (tid < ROWS) {
        float s = b_fc[0];
        const float* rr = red + tid * Hsz;
        #pragma unroll
        for (int k = 0; k < Hsz; ++k) s += rr[k];
        out[base + tid] = s;
    }
}

extern "C" void kernel_launch(void* const* d_in, const int* in_sizes, int n_in,
                              void* d_out, int out_size)
{
    const float* x    = (const float*)d_in[0];
    const float* W_in = (const float*)d_in[1];
    const float* b_in = (const float*)d_in[2];
    const float* W_r  = (const float*)d_in[3];
    const float* b_r  = (const float*)d_in[4];
    const float* W_fc = (const float*)d_in[5];
    const float* b_fc = (const float*)d_in[6];
    float* out = (float*)d_out;

    const size_t smem = (size_t)(2 * Hsz * PAD + 2 * ROWS * Hsz + ROWS * Dsz) * sizeof(float);
    cudaFuncSetAttribute(ltc_kernel, cudaFuncAttributeMaxDynamicSharedMemorySize, (int)smem);

    ltc_kernel<<<Bsz / ROWS, THREADS, smem>>>(x, W_in, b_in, W_r, b_r, W_fc, b_fc, out);
}